// round 10
// baseline (speedup 1.0000x reference)
#include <cuda_runtime.h>
#include <cuda_bf16.h>
#include <math.h>
#include <stdint.h>
#include <stddef.h>

#define NTRAJ  256
#define NTP    512
#define LATENT 256
#define INPUT  128
#define NUNITS 256
#define GIN    (LATENT + INPUT)   // 384
#define DEC_OUT 128
#define NSTEP  (NTP - 1)          // 511

#define G       8                 // trajectories per cluster (doubled: byte reuse)
#define NCLU    (NTRAJ / G)       // 32 clusters
#define NBLK    (NCLU * 2)        // 64 CTAs (2 per cluster, K-split)
#define THREADS 512               // intra-CTA split-K x2 on top of cluster split

typedef unsigned long long u64;

union F2U { float2 f; u64 u; };

__device__ __forceinline__ u64 ffma2(u64 a, u64 b, u64 c) {
    u64 d;
    asm("fma.rn.f32x2 %0, %1, %2, %3;" : "=l"(d) : "l"(a), "l"(b), "l"(c));
    return d;
}
__device__ __forceinline__ float lanesum(u64 v) {
    F2U r; r.u = v; return r.f.x + r.f.y;
}
__device__ __forceinline__ float sigmoid_fast(float x) {
    return __fdividef(1.f, 1.f + __expf(-x));
}
__device__ __forceinline__ uint32_t smem_u32(const void* p) {
    uint32_t a;
    asm("{ .reg .u64 t; cvta.to.shared.u64 t, %1; cvt.u32.u64 %0, t; }" : "=r"(a) : "l"(p));
    return a;
}
__device__ __forceinline__ uint32_t ctarank() {
    uint32_t r; asm("mov.u32 %0, %%cluster_ctarank;" : "=r"(r)); return r;
}
__device__ __forceinline__ uint32_t mapa_u32(uint32_t addr, uint32_t rank) {
    uint32_t r;
    asm("mapa.shared::cluster.u32 %0, %1, %2;" : "=r"(r) : "r"(addr), "r"(rank));
    return r;
}
__device__ __forceinline__ void st_peer_f4(uint32_t dst, float a, float b, float c, float d) {
    F2U lo, hi; lo.f = make_float2(a, b); hi.f = make_float2(c, d);
    asm volatile("st.shared::cluster.u64 [%0], %1;" :: "r"(dst),     "l"(lo.u) : "memory");
    asm volatile("st.shared::cluster.u64 [%0], %1;" :: "r"(dst + 8), "l"(hi.u) : "memory");
}
__device__ __forceinline__ void st_peer_f8(uint32_t dst, const float* v) {
#pragma unroll
    for (int i = 0; i < 4; i++) {
        F2U x; x.f = make_float2(v[2 * i], v[2 * i + 1]);
        asm volatile("st.shared::cluster.u64 [%0], %1;" :: "r"(dst + 8 * i), "l"(x.u) : "memory");
    }
}
__device__ __forceinline__ void ld8(float* d, const float* s) {
    *(float4*)d       = *(const float4*)s;
    *(float4*)(d + 4) = *(const float4*)(s + 4);
}
__device__ __forceinline__ void st8(float* d, const float* s) {
    *(float4*)d       = *(const float4*)s;
    *(float4*)(d + 4) = *(const float4*)(s + 4);
}
#define CLUSTER_SYNC() do { \
    asm volatile("barrier.cluster.arrive.aligned;" ::: "memory"); \
    asm volatile("barrier.cluster.wait.aligned;"   ::: "memory"); \
} while (0)

// ---------------------------------------------------------------------------
// Packed weights: float4 along k: W4[k4][j] = W[4k4..4k4+3][j], as ulonglong2.
// ---------------------------------------------------------------------------
#define SZ_M384 (96 * 256)
#define SZ_M256 (64 * 256)
#define SZ_DEC  (64 * 128)
#define OFF_UG1  0
#define OFF_UGT1 (OFF_UG1  + SZ_M384)
#define OFF_RG1  (OFF_UGT1 + SZ_M384)
#define OFF_NS1  (OFF_RG1  + SZ_M384)
#define OFF_UG2  (OFF_NS1  + SZ_M384)
#define OFF_UGT2 (OFF_UG2  + SZ_M256)
#define OFF_RG2  (OFF_UGT2 + SZ_M256)
#define OFF_NS2  (OFF_RG2  + SZ_M256)
#define OFF_DK1  (OFF_NS2  + SZ_M256)
#define OFF_DEC  (OFF_DK1  + SZ_M256)
#define WP_TOTAL (OFF_DEC  + SZ_DEC)

__device__ ulonglong2 g_wp[WP_TOTAL];

__global__ void pack_kernel(
    const float* ug1, const float* ugt1, const float* rg1, const float* ns1,
    const float* ug2, const float* ugt2, const float* rg2, const float* ns2,
    const float* dk1, const float* decw)
{
    const float* srcs[10] = {ug1, ugt1, rg1, ns1, ug2, ugt2, rg2, ns2, dk1, decw};
    const int offs[11] = {OFF_UG1, OFF_UGT1, OFF_RG1, OFF_NS1, OFF_UG2, OFF_UGT2,
                          OFF_RG2, OFF_NS2, OFF_DK1, OFF_DEC, WP_TOTAL};
    const int Ns[10] = {256,256,256,256,256,256,256,256,256,128};

    int idx = blockIdx.x * blockDim.x + threadIdx.x;
    if (idx >= WP_TOTAL) return;
    int m = 0;
    while (idx >= offs[m + 1]) m++;
    int local = idx - offs[m];
    int N = Ns[m];
    int k4 = local / N, j = local % N;
    const float* S = srcs[m];
    F2U lo, hi;
    lo.f = make_float2(S[(4 * k4 + 0) * N + j], S[(4 * k4 + 1) * N + j]);
    hi.f = make_float2(S[(4 * k4 + 2) * N + j], S[(4 * k4 + 3) * N + j]);
    g_wp[idx] = make_ulonglong2(lo.u, hi.u);
}

// ---------------------------------------------------------------------------
// Partial packed GEMV, shared activation input. A/B register double-buffer.
// ---------------------------------------------------------------------------
template <int K2H, int NG, int N, int CU>
__device__ __forceinline__ void gemv_part(
    float (&res)[NG][G],
    const ulonglong2* const (&Wv)[NG],
    const float* act, int astride, int j)
{
    constexpr int K4 = K2H / 2;
    constexpr int CH = K4 / CU;
    static_assert(CH % 2 == 0, "chunks must be even");

    u64 acc[NG][G];
#pragma unroll
    for (int ng = 0; ng < NG; ng++)
#pragma unroll
        for (int g = 0; g < G; g++) acc[ng][g] = 0ull;

    ulonglong2 wA[NG][CU], wB[NG][CU];

    auto LD = [&](ulonglong2 (&w)[NG][CU], int c) {
#pragma unroll
        for (int ng = 0; ng < NG; ng++)
#pragma unroll
            for (int cu = 0; cu < CU; cu++)
                w[ng][cu] = Wv[ng][(c * CU + cu) * N + j];
    };
    auto CP = [&](ulonglong2 (&w)[NG][CU], int c) {
#pragma unroll
        for (int cu = 0; cu < CU; cu++) {
            int k4 = c * CU + cu;
#pragma unroll
            for (int g = 0; g < G; g++) {
                ulonglong2 av = *(const ulonglong2*)(act + g * astride + 4 * k4);
#pragma unroll
                for (int ng = 0; ng < NG; ng++) {
                    acc[ng][g] = ffma2(av.x, w[ng][cu].x, acc[ng][g]);
                    acc[ng][g] = ffma2(av.y, w[ng][cu].y, acc[ng][g]);
                }
            }
        }
    };

    LD(wA, 0);
#pragma unroll 1
    for (int cc = 0; cc < CH / 2; cc++) {
        LD(wB, 2 * cc + 1);
        CP(wA, 2 * cc);
        if (cc + 1 < CH / 2) LD(wA, 2 * cc + 2);
        CP(wB, 2 * cc + 1);
    }

#pragma unroll
    for (int ng = 0; ng < NG; ng++)
#pragma unroll
        for (int g = 0; g < G; g++) res[ng][g] = lanesum(acc[ng][g]);
}

// Decoder partial: 4 trajectories, 16 k4 rows (one K-quarter), N=128.
__device__ __forceinline__ void gemv_dec4(
    float (&res)[4], const ulonglong2* W,
    const float* a0p, const float* a1p, const float* a2p, const float* a3p, int jd)
{
    constexpr int CU = 4, CH = 4;  // 16 k4 rows
    u64 acc[4] = {0ull, 0ull, 0ull, 0ull};
    ulonglong2 wA[CU], wB[CU];
    const float* ap[4] = {a0p, a1p, a2p, a3p};

    auto LD = [&](ulonglong2 (&w)[CU], int c) {
#pragma unroll
        for (int cu = 0; cu < CU; cu++) w[cu] = W[(c * CU + cu) * 128 + jd];
    };
    auto CP = [&](ulonglong2 (&w)[CU], int c) {
#pragma unroll
        for (int cu = 0; cu < CU; cu++) {
            int k4 = c * CU + cu;
#pragma unroll
            for (int g = 0; g < 4; g++) {
                ulonglong2 a = *(const ulonglong2*)(ap[g] + 4 * k4);
                acc[g] = ffma2(a.x, w[cu].x, acc[g]);
                acc[g] = ffma2(a.y, w[cu].y, acc[g]);
            }
        }
    };

    LD(wA, 0);
#pragma unroll 1
    for (int cc = 0; cc < CH / 2; cc++) {
        LD(wB, 2 * cc + 1);
        CP(wA, 2 * cc);
        if (cc + 1 < CH / 2) LD(wA, 2 * cc + 2);
        CP(wB, 2 * cc + 1);
    }
#pragma unroll
    for (int g = 0; g < 4; g++) res[g] = lanesum(acc[g]);
}

// ---------------------------------------------------------------------------
// Shared memory layout (dynamic).  ~135 KB
// ---------------------------------------------------------------------------
struct __align__(16) SM {
    float sy  [G * LATENT];
    float syt [G * LATENT];
    float syc [G * GIN];
    float shh0[G * NUNITS];
    float shh1[G * NUNITS];
    float shh2[G * NUNITS];
    float P[3][256][G];         // intra-CTA quarter partials (q1 writes)
    float A[3][256][G];         // cluster exchange set A (peer writes)
    float B[3][256][G];         // cluster exchange set B (peer writes)
    float D[128][G];            // decoder rank partial (rank1 -> rank0)
    float Pd[128][G];           // decoder intra-CTA partial (kq1 writes)
    float sdt[G], sdecay[G], smask[G];
    float sred[8][G];
};
#define SMEM_BYTES ((int)sizeof(SM))

__global__ void __cluster_dims__(2, 1, 1) __launch_bounds__(THREADS, 1)
rnn_decay_kernel(
    const float* __restrict__ data, const float* __restrict__ ts,
    const float* __restrict__ ug_b1,  const float* __restrict__ ug_b2,
    const float* __restrict__ ugt_b1, const float* __restrict__ ugt_b2,
    const float* __restrict__ rg_b1,  const float* __restrict__ rg_b2,
    const float* __restrict__ ns_b1,  const float* __restrict__ ns_b2,
    const float* __restrict__ dk_b1,  const float* __restrict__ dk_w2,
    const float* __restrict__ dk_b2,  const float* __restrict__ dec_b,
    float* __restrict__ out)
{
    extern __shared__ __align__(16) char smraw[];
    SM* sm = reinterpret_cast<SM*>(smraw);

    const int tid  = threadIdx.x;        // 0..511
    const int j    = tid & 255;          // output unit
    const int q    = tid >> 8;           // intra-CTA k-quarter
    const int lane = tid & 31, warp = tid >> 5;
    const uint32_t rank = ctarank();     // k-half owned by this CTA
    const int tb   = (blockIdx.x >> 1) * G;

    const uint32_t sb = smem_u32(sm);
    const uint32_t pb = mapa_u32(sb, rank ^ 1u);
    const uint32_t pA = pb + (uint32_t)offsetof(SM, A);
    const uint32_t pB = pb + (uint32_t)offsetof(SM, B);
    const uint32_t pD = pb + (uint32_t)offsetof(SM, D);

    const ulonglong2* WP = g_wp;

    // K-slice offsets for this (rank, q)
    const int r384 = (rank * 48 + q * 24) * 256;  // 384-row matrices
    const int r256 = (rank * 32 + q * 16) * 256;  // 256-row matrices
    const int a384 = rank * 192 + q * 96;         // act offset, 384 inputs
    const int a256 = rank * 128 + q * 64;         // act offset, 256 inputs

    // decoder mapping: sel 0..3 = (k-quarter, trajectory quad)
    const int jd = tid & 127, sel = tid >> 7;
    const int gq = (sel & 1) * 4, kq = sel >> 1;

    float* out_prev = out;
    float* out_vol  = out + (size_t)NTRAJ * LATENT;
    float* out_dts  = out + (size_t)NTRAJ * LATENT + (size_t)NTRAJ * NSTEP * DEC_OUT;

    for (int i = tid; i < G * LATENT; i += THREADS) { sm->sy[i] = 0.f; sm->syt[i] = 0.f; }

    for (int t = 0; t < NTP; t++) {
        CLUSTER_SYNC();   // S0

        // ---- setup: xh -> syc tail, mask, dt ----
        for (int i = tid; i < G * INPUT; i += THREADS) {
            int g = i >> 7, jj = i & 127;
            sm->syc[g * GIN + LATENT + jj] =
                data[((size_t)(tb + g) * NTP + t) * (2 * INPUT) + jj];
        }
        if (warp < G) {
            const float* xp = data + ((size_t)(tb + warp) * NTP + t) * (2 * INPUT) + INPUT;
            float s = xp[lane] + xp[lane + 32] + xp[lane + 64] + xp[lane + 96];
#pragma unroll
            for (int off = 16; off; off >>= 1) s += __shfl_xor_sync(0xffffffffu, s, off);
            if (lane == 0) sm->smask[warp] = (s > 0.f) ? 1.f : 0.f;
        }
        if (tid < G && t > 0) {
            float d = ts[(size_t)(tb + tid) * NTP + t] - ts[(size_t)(tb + tid) * NTP + t - 1];
            sm->sdt[tid] = d;
            if (rank == 0)
                out_dts[(size_t)(tb + tid) * NSTEP + (t - 1)] = d;
        }
        __syncthreads();

        float u[G], ut[G];       // valid on q0 after S3
        float pdec[4], dtot[4];  // decoder partials

        if (t > 0) {
            // ---- decay layer1 (256->256) ----
            {
                const ulonglong2* Wd[1] = { WP + OFF_DK1 + r256 };
                float p[1][G];
                gemv_part<32, 1, 256, 2>(p, Wd, sm->sy + a256, LATENT, j);
                if (q) st8(&sm->P[0][j][0], p[0]);
                __syncthreads();
                if (!q) {
                    float lp[G]; ld8(lp, &sm->P[0][j][0]);
#pragma unroll
                    for (int g = 0; g < G; g++) p[0][g] += lp[g];
                    st_peer_f8(pA + (uint32_t)(j * G * 4), p[0]);
                }
                CLUSTER_SYNC();  // S1
                if (!q) {
                    float bv = dk_b1[j];
                    float pr[G]; ld8(pr, &sm->A[0][j][0]);
#pragma unroll
                    for (int g = 0; g < G; g++)
                        sm->shh0[g * NUNITS + j] = fmaxf(p[0][g] + pr[g] + bv, 0.f);
                }
                __syncthreads();
            }
            // ---- decay layer2: 256->1 (q0 warps) ----
            if (!q) {
                float v[G];
                float w2v = dk_w2[j];
#pragma unroll
                for (int g = 0; g < G; g++) v[g] = sm->shh0[g * NUNITS + j] * w2v;
#pragma unroll
                for (int off = 16; off; off >>= 1)
#pragma unroll
                    for (int g = 0; g < G; g++) v[g] += __shfl_xor_sync(0xffffffffu, v[g], off);
                if (lane == 0)
#pragma unroll
                    for (int g = 0; g < G; g++) sm->sred[warp][g] = v[g];
            }
            __syncthreads();
            if (tid < G) {
                float s = dk_b2[0];
#pragma unroll
                for (int w = 0; w < 8; w++) s += sm->sred[w][tid];
                sm->sdecay[tid] = fmaxf(s, 0.f);
            }
            __syncthreads();

            // ---- elementwise decay: 2048 items over 512 threads ----
            for (int it = tid; it < G * 256; it += THREADS) {
                int g = it >> 8, jj = it & 255;
                float d  = sm->sdecay[g] * sm->sdt[g];
                float e1 = __expf(-0.5f * d);
                float e2 = __expf(-d);
                float yv = sm->sy[g * LATENT + jj], ytv = sm->syt[g * LATENT + jj];
                float df = yv - ytv;
                sm->shh0[g * NUNITS + jj] = ytv + df * (0.5f * (1.f + e1));  // mean_ydec
                float yend = ytv + df * e2;
                sm->sy[g * LATENT + jj] = yend;
                sm->syc[g * GIN + jj]   = yend;
            }
            __syncthreads();

            // ---- decoder partial (K-quarter of mean_ydec), 4 trajs/thread ----
            {
                const ulonglong2* Wd = WP + OFF_DEC + (rank * 32 + kq * 16) * 128;
                int ao = rank * 128 + kq * 64;
                gemv_dec4(pdec, Wd,
                          sm->shh0 + (gq + 0) * NUNITS + ao,
                          sm->shh0 + (gq + 1) * NUNITS + ao,
                          sm->shh0 + (gq + 2) * NUNITS + ao,
                          sm->shh0 + (gq + 3) * NUNITS + ao, jd);
                if (kq) {
#pragma unroll
                    for (int i = 0; i < 4; i++) sm->Pd[jd][gq + i] = pdec[i];
                }
            }
        } else {
            for (int it = tid; it < G * 256; it += THREADS) {
                int g = it >> 8, jj = it & 255;
                sm->syc[g * GIN + jj] = 0.f;
            }
            __syncthreads();
        }

        // ---- gate layer1: ug/ugt/rg (384->256 x3, sequential NG=1) ----
        {
            const ulonglong2* W0[1] = { WP + OFF_UG1  + r384 };
            const ulonglong2* W1[1] = { WP + OFF_UGT1 + r384 };
            const ulonglong2* W2[1] = { WP + OFF_RG1  + r384 };
            float p0[1][G], p1[1][G], p2[1][G];
            gemv_part<48, 1, 256, 2>(p0, W0, sm->syc + a384, GIN, j);
            if (q) st8(&sm->P[0][j][0], p0[0]);
            gemv_part<48, 1, 256, 2>(p1, W1, sm->syc + a384, GIN, j);
            if (q) st8(&sm->P[1][j][0], p1[0]);
            gemv_part<48, 1, 256, 2>(p2, W2, sm->syc + a384, GIN, j);
            if (q) st8(&sm->P[2][j][0], p2[0]);
            __syncthreads();   // also publishes Pd (decoder) writes
            if (!q) {
                float lp[G];
                ld8(lp, &sm->P[0][j][0]);
#pragma unroll
                for (int g = 0; g < G; g++) p0[0][g] += lp[g];
                st_peer_f8(pB + (uint32_t)((0 * 256 + j) * G * 4), p0[0]);
                ld8(lp, &sm->P[1][j][0]);
#pragma unroll
                for (int g = 0; g < G; g++) p1[0][g] += lp[g];
                st_peer_f8(pB + (uint32_t)((1 * 256 + j) * G * 4), p1[0]);
                ld8(lp, &sm->P[2][j][0]);
#pragma unroll
                for (int g = 0; g < G; g++) p2[0][g] += lp[g];
                st_peer_f8(pB + (uint32_t)((2 * 256 + j) * G * 4), p2[0]);
                if (t > 0) {
#pragma unroll
                    for (int i = 0; i < 4; i++) dtot[i] = pdec[i] + sm->Pd[jd][gq + i];
                    if (rank == 1)
                        st_peer_f4(pD + (uint32_t)((jd * G + gq) * 4),
                                   dtot[0], dtot[1], dtot[2], dtot[3]);
                }
            }
            CLUSTER_SYNC();  // S2
            if (!q) {
                float b0 = ug_b1[j], b1 = ugt_b1[j], b2 = rg_b1[j];
                float r[G];
                ld8(r, &sm->B[0][j][0]);
#pragma unroll
                for (int g = 0; g < G; g++)
                    sm->shh0[g * NUNITS + j] = tanhf(p0[0][g] + r[g] + b0);
                ld8(r, &sm->B[1][j][0]);
#pragma unroll
                for (int g = 0; g < G; g++)
                    sm->shh1[g * NUNITS + j] = tanhf(p1[0][g] + r[g] + b1);
                ld8(r, &sm->B[2][j][0]);
#pragma unroll
                for (int g = 0; g < G; g++)
                    sm->shh2[g * NUNITS + j] = tanhf(p2[0][g] + r[g] + b2);
                if (t > 0 && rank == 0) {
                    float bv = dec_b[jd];
#pragma unroll
                    for (int i = 0; i < 4; i++)
                        out_vol[((size_t)(tb + gq + i) * NSTEP + (t - 1)) * DEC_OUT + jd] =
                            dtot[i] + sm->D[jd][gq + i] + bv;
                }
            }
            __syncthreads();
        }

        // ---- gate layer2 x3 (256->256, sequential NG=1, per-matrix acts) ----
        {
            const ulonglong2* W0[1] = { WP + OFF_UG2  + r256 };
            const ulonglong2* W1[1] = { WP + OFF_UGT2 + r256 };
            const ulonglong2* W2[1] = { WP + OFF_RG2  + r256 };
            float p0[1][G], p1[1][G], p2[1][G];
            gemv_part<32, 1, 256, 2>(p0, W0, sm->shh0 + a256, NUNITS, j);
            if (q) st8(&sm->P[0][j][0], p0[0]);
            gemv_part<32, 1, 256, 2>(p1, W1, sm->shh1 + a256, NUNITS, j);
            if (q) st8(&sm->P[1][j][0], p1[0]);
            gemv_part<32, 1, 256, 2>(p2, W2, sm->shh2 + a256, NUNITS, j);
            if (q) st8(&sm->P[2][j][0], p2[0]);
            __syncthreads();
            if (!q) {
                float lp[G];
                ld8(lp, &sm->P[0][j][0]);
#pragma unroll
                for (int g = 0; g < G; g++) p0[0][g] += lp[g];
                st_peer_f8(pA + (uint32_t)((0 * 256 + j) * G * 4), p0[0]);
                ld8(lp, &sm->P[1][j][0]);
#pragma unroll
                for (int g = 0; g < G; g++) p1[0][g] += lp[g];
                st_peer_f8(pA + (uint32_t)((1 * 256 + j) * G * 4), p1[0]);
                ld8(lp, &sm->P[2][j][0]);
#pragma unroll
                for (int g = 0; g < G; g++) p2[0][g] += lp[g];
                st_peer_f8(pA + (uint32_t)((2 * 256 + j) * G * 4), p2[0]);
            }
            CLUSTER_SYNC();  // S3
            if (!q) {
                float b0 = ug_b2[j], b1 = ugt_b2[j], b2 = rg_b2[j];
                float r[G];
                ld8(r, &sm->A[0][j][0]);
#pragma unroll
                for (int g = 0; g < G; g++) u[g] = sigmoid_fast(p0[0][g] + r[g] + b0);
                ld8(r, &sm->A[1][j][0]);
#pragma unroll
                for (int g = 0; g < G; g++) ut[g] = sigmoid_fast(p1[0][g] + r[g] + b1);
                ld8(r, &sm->A[2][j][0]);
#pragma unroll
                for (int g = 0; g < G; g++)
                    sm->syc[g * GIN + j] *= sigmoid_fast(p2[0][g] + r[g] + b2);
            }
            __syncthreads();
        }

        // ---- new_state layer1 (384->256) ----
        {
            const ulonglong2* Wg[1] = { WP + OFF_NS1 + r384 };
            float p[1][G];
            gemv_part<48, 1, 256, 2>(p, Wg, sm->syc + a384, GIN, j);
            if (q) st8(&sm->P[0][j][0], p[0]);
            __syncthreads();
            if (!q) {
                float lp[G]; ld8(lp, &sm->P[0][j][0]);
#pragma unroll
                for (int g = 0; g < G; g++) p[0][g] += lp[g];
                st_peer_f8(pB + (uint32_t)(j * G * 4), p[0]);
            }
            CLUSTER_SYNC();  // S4
            if (!q) {
                float bv = ns_b1[j];
                float pr[G]; ld8(pr, &sm->B[0][j][0]);
#pragma unroll
                for (int g = 0; g < G; g++)
                    sm->shh0[g * NUNITS + j] = tanhf(p[0][g] + pr[g] + bv);
            }
            __syncthreads();
        }

        // ---- new_state layer2 (256->256) + masked update ----
        {
            const ulonglong2* Wg[1] = { WP + OFF_NS2 + r256 };
            float p[1][G];
            gemv_part<32, 1, 256, 2>(p, Wg, sm->shh0 + a256, NUNITS, j);
            if (q) st8(&sm->P[0][j][0], p[0]);
            __syncthreads();
            if (!q) {
                float lp[G]; ld8(lp, &sm->P[0][j][0]);
#pragma unroll
                for (int g = 0; g < G; g++) p[0][g] += lp[g];
                st_peer_f8(pA + (uint32_t)(j * G * 4), p[0]);
            }
            CLUSTER_SYNC();  // S5
            if (!q) {
                float bv = ns_b2[j];
                float pr[G]; ld8(pr, &sm->A[0][j][0]);
#pragma unroll
                for (int g = 0; g < G; g++) {
                    float nsv  = p[0][g] + pr[g] + bv;
                    float m    = sm->smask[g];
                    float yend = sm->sy[g * LATENT + j], ytv = sm->syt[g * LATENT + j];
                    float ny   = (1.f - u[g])  * nsv + u[g]  * yend;
                    float nyt  = (1.f - ut[g]) * nsv + ut[g] * ytv;
                    sm->sy [g * LATENT + j] = m * ny  + (1.f - m) * yend;
                    sm->syt[g * LATENT + j] = m * nyt + (1.f - m) * ytv;
                }
            }
        }
        // S0 of next iteration publishes sy/syt and protects buffer reuse
    }

    CLUSTER_SYNC();
    if (rank == 0 && !q) {
#pragma unroll
        for (int g = 0; g < G; g++)
            out_prev[(size_t)(tb + g) * LATENT + j] = sm->sy[g * LATENT + j];
    }
}

extern "C" void kernel_launch(void* const* d_in, const int* in_sizes, int n_in,
                              void* d_out, int out_size) {
    const float* data   = (const float*)d_in[0];
    const float* ts     = (const float*)d_in[1];
    const float* ug_w1  = (const float*)d_in[2];
    const float* ug_b1  = (const float*)d_in[3];
    const float* ug_w2  = (const float*)d_in[4];
    const float* ug_b2  = (const float*)d_in[5];
    const float* ugt_w1 = (const float*)d_in[6];
    const float* ugt_b1 = (const float*)d_in[7];
    const float* ugt_w2 = (const float*)d_in[8];
    const float* ugt_b2 = (const float*)d_in[9];
    const float* rg_w1  = (const float*)d_in[10];
    const float* rg_b1  = (const float*)d_in[11];
    const float* rg_w2  = (const float*)d_in[12];
    const float* rg_b2  = (const float*)d_in[13];
    // d_in[14..17] = rgt_* : unused by the reference
    const float* ns_w1  = (const float*)d_in[18];
    const float* ns_b1  = (const float*)d_in[19];
    const float* ns_w2  = (const float*)d_in[20];
    const float* ns_b2  = (const float*)d_in[21];
    const float* dk_w1  = (const float*)d_in[22];
    const float* dk_b1  = (const float*)d_in[23];
    const float* dk_w2  = (const float*)d_in[24];
    const float* dk_b2  = (const float*)d_in[25];
    const float* dec_w  = (const float*)d_in[26];
    const float* dec_b  = (const float*)d_in[27];

    cudaFuncSetAttribute(rnn_decay_kernel,
                         cudaFuncAttributeMaxDynamicSharedMemorySize, SMEM_BYTES);

    pack_kernel<<<(WP_TOTAL + 255) / 256, 256>>>(
        ug_w1, ugt_w1, rg_w1, ns_w1, ug_w2, ugt_w2, rg_w2, ns_w2, dk_w1, dec_w);

    rnn_decay_kernel<<<NBLK, THREADS, SMEM_BYTES>>>(
        data, ts,
        ug_b1, ug_b2, ugt_b1, ugt_b2, rg_b1, rg_b2,
        ns_b1, ns_b2, dk_b1, dk_w2, dk_b2, dec_b,
        (float*)d_out);
}

// round 11
// speedup vs baseline: 1.3092x; 1.3092x over previous
#include <cuda_runtime.h>
#include <cuda_bf16.h>
#include <math.h>
#include <stdint.h>
#include <stddef.h>

#define NTRAJ  256
#define NTP    512
#define LATENT 256
#define INPUT  128
#define NUNITS 256
#define GIN    (LATENT + INPUT)   // 384
#define DEC_OUT 128
#define NSTEP  (NTP - 1)          // 511

#define G       4                 // trajectories per cluster
#define NCLU    (NTRAJ / G)       // 64 clusters
#define NBLK    (NCLU * 2)        // 128 CTAs (2 per cluster, K-split)
#define THREADS 512               // intra-CTA split-K x2 (quarter-K per thread)

typedef unsigned long long u64;

union F2U { float2 f; u64 u; };

__device__ __forceinline__ u64 ffma2(u64 a, u64 b, u64 c) {
    u64 d;
    asm("fma.rn.f32x2 %0, %1, %2, %3;" : "=l"(d) : "l"(a), "l"(b), "l"(c));
    return d;
}
__device__ __forceinline__ float lanesum(u64 v) {
    F2U r; r.u = v; return r.f.x + r.f.y;
}
__device__ __forceinline__ float sigmoid_fast(float x) {
    return __fdividef(1.f, 1.f + __expf(-x));
}
__device__ __forceinline__ uint32_t smem_u32(const void* p) {
    uint32_t a;
    asm("{ .reg .u64 t; cvta.to.shared.u64 t, %1; cvt.u32.u64 %0, t; }" : "=r"(a) : "l"(p));
    return a;
}
__device__ __forceinline__ uint32_t ctarank() {
    uint32_t r; asm("mov.u32 %0, %%cluster_ctarank;" : "=r"(r)); return r;
}
__device__ __forceinline__ uint32_t mapa_u32(uint32_t addr, uint32_t rank) {
    uint32_t r;
    asm("mapa.shared::cluster.u32 %0, %1, %2;" : "=r"(r) : "r"(addr), "r"(rank));
    return r;
}
__device__ __forceinline__ void st_peer_f4(uint32_t dst, float a, float b, float c, float d) {
    F2U lo, hi; lo.f = make_float2(a, b); hi.f = make_float2(c, d);
    asm volatile("st.shared::cluster.u64 [%0], %1;" :: "r"(dst),     "l"(lo.u) : "memory");
    asm volatile("st.shared::cluster.u64 [%0], %1;" :: "r"(dst + 8), "l"(hi.u) : "memory");
}
__device__ __forceinline__ void st_peer_f2(uint32_t dst, float a, float b) {
    F2U lo; lo.f = make_float2(a, b);
    asm volatile("st.shared::cluster.u64 [%0], %1;" :: "r"(dst), "l"(lo.u) : "memory");
}
#define CLUSTER_SYNC() do { \
    asm volatile("barrier.cluster.arrive.aligned;" ::: "memory"); \
    asm volatile("barrier.cluster.wait.aligned;"   ::: "memory"); \
} while (0)

// ---------------------------------------------------------------------------
// Packed weights: float4 along k: W4[k4][j] = W[4k4..4k4+3][j], as ulonglong2.
// ---------------------------------------------------------------------------
#define SZ_M384 (96 * 256)
#define SZ_M256 (64 * 256)
#define SZ_DEC  (64 * 128)
#define OFF_UG1  0
#define OFF_UGT1 (OFF_UG1  + SZ_M384)
#define OFF_RG1  (OFF_UGT1 + SZ_M384)
#define OFF_NS1  (OFF_RG1  + SZ_M384)
#define OFF_UG2  (OFF_NS1  + SZ_M384)
#define OFF_UGT2 (OFF_UG2  + SZ_M256)
#define OFF_RG2  (OFF_UGT2 + SZ_M256)
#define OFF_NS2  (OFF_RG2  + SZ_M256)
#define OFF_DK1  (OFF_NS2  + SZ_M256)
#define OFF_DEC  (OFF_DK1  + SZ_M256)
#define WP_TOTAL (OFF_DEC  + SZ_DEC)

__device__ ulonglong2 g_wp[WP_TOTAL];

__global__ void pack_kernel(
    const float* ug1, const float* ugt1, const float* rg1, const float* ns1,
    const float* ug2, const float* ugt2, const float* rg2, const float* ns2,
    const float* dk1, const float* decw)
{
    const float* srcs[10] = {ug1, ugt1, rg1, ns1, ug2, ugt2, rg2, ns2, dk1, decw};
    const int offs[11] = {OFF_UG1, OFF_UGT1, OFF_RG1, OFF_NS1, OFF_UG2, OFF_UGT2,
                          OFF_RG2, OFF_NS2, OFF_DK1, OFF_DEC, WP_TOTAL};
    const int Ns[10] = {256,256,256,256,256,256,256,256,256,128};

    int idx = blockIdx.x * blockDim.x + threadIdx.x;
    if (idx >= WP_TOTAL) return;
    int m = 0;
    while (idx >= offs[m + 1]) m++;
    int local = idx - offs[m];
    int N = Ns[m];
    int k4 = local / N, j = local % N;
    const float* S = srcs[m];
    F2U lo, hi;
    lo.f = make_float2(S[(4 * k4 + 0) * N + j], S[(4 * k4 + 1) * N + j]);
    hi.f = make_float2(S[(4 * k4 + 2) * N + j], S[(4 * k4 + 3) * N + j]);
    g_wp[idx] = make_ulonglong2(lo.u, hi.u);
}

// ---------------------------------------------------------------------------
// Partial packed GEMV, single act vector. A/B register double-buffer.
// ---------------------------------------------------------------------------
template <int K2H, int NG, int N, int CU>
__device__ __forceinline__ void gemv_part(
    float (&res)[NG][G],
    const ulonglong2* const (&Wv)[NG],
    const float* act, int astride, int j)
{
    constexpr int K4 = K2H / 2;
    constexpr int CH = K4 / CU;
    static_assert(CH % 2 == 0, "chunks must be even");

    u64 acc[NG][G];
#pragma unroll
    for (int ng = 0; ng < NG; ng++)
#pragma unroll
        for (int g = 0; g < G; g++) acc[ng][g] = 0ull;

    ulonglong2 wA[NG][CU], wB[NG][CU];

    auto LD = [&](ulonglong2 (&w)[NG][CU], int c) {
#pragma unroll
        for (int ng = 0; ng < NG; ng++)
#pragma unroll
            for (int cu = 0; cu < CU; cu++)
                w[ng][cu] = Wv[ng][(c * CU + cu) * N + j];
    };
    auto CP = [&](ulonglong2 (&w)[NG][CU], int c) {
#pragma unroll
        for (int cu = 0; cu < CU; cu++) {
            int k4 = c * CU + cu;
#pragma unroll
            for (int g = 0; g < G; g++) {
                ulonglong2 av = *(const ulonglong2*)(act + g * astride + 4 * k4);
#pragma unroll
                for (int ng = 0; ng < NG; ng++) {
                    acc[ng][g] = ffma2(av.x, w[ng][cu].x, acc[ng][g]);
                    acc[ng][g] = ffma2(av.y, w[ng][cu].y, acc[ng][g]);
                }
            }
        }
    };

    LD(wA, 0);
#pragma unroll 1
    for (int cc = 0; cc < CH / 2; cc++) {
        LD(wB, 2 * cc + 1);
        CP(wA, 2 * cc);
        if (cc + 1 < CH / 2) LD(wA, 2 * cc + 2);
        CP(wB, 2 * cc + 1);
    }

#pragma unroll
    for (int ng = 0; ng < NG; ng++)
#pragma unroll
        for (int g = 0; g < G; g++) res[ng][g] = lanesum(acc[ng][g]);
}

// Dual-act GEMV: one weight stream, two activation vectors (yt and df).
template <int K2H, int N, int CU>
__device__ __forceinline__ void gemv_dual(
    float (&rA)[G], float (&rB)[G],
    const ulonglong2* W,
    const float* actA, const float* actB, int astride, int j)
{
    constexpr int K4 = K2H / 2;
    constexpr int CH = K4 / CU;
    static_assert(CH % 2 == 0, "chunks must be even");

    u64 aA[G], aB[G];
#pragma unroll
    for (int g = 0; g < G; g++) { aA[g] = 0ull; aB[g] = 0ull; }

    ulonglong2 wA[CU], wB[CU];

    auto LD = [&](ulonglong2 (&w)[CU], int c) {
#pragma unroll
        for (int cu = 0; cu < CU; cu++) w[cu] = W[(c * CU + cu) * N + j];
    };
    auto CP = [&](ulonglong2 (&w)[CU], int c) {
#pragma unroll
        for (int cu = 0; cu < CU; cu++) {
            int k4 = c * CU + cu;
#pragma unroll
            for (int g = 0; g < G; g++) {
                ulonglong2 vA = *(const ulonglong2*)(actA + g * astride + 4 * k4);
                ulonglong2 vB = *(const ulonglong2*)(actB + g * astride + 4 * k4);
                aA[g] = ffma2(vA.x, w[cu].x, aA[g]);
                aA[g] = ffma2(vA.y, w[cu].y, aA[g]);
                aB[g] = ffma2(vB.x, w[cu].x, aB[g]);
                aB[g] = ffma2(vB.y, w[cu].y, aB[g]);
            }
        }
    };

    LD(wA, 0);
#pragma unroll 1
    for (int cc = 0; cc < CH / 2; cc++) {
        LD(wB, 2 * cc + 1);
        CP(wA, 2 * cc);
        if (cc + 1 < CH / 2) LD(wA, 2 * cc + 2);
        CP(wB, 2 * cc + 1);
    }

#pragma unroll
    for (int g = 0; g < G; g++) { rA[g] = lanesum(aA[g]); rB[g] = lanesum(aB[g]); }
}

// Per-matrix-activation variant (gate layer 2).
template <int K2H, int NG, int N>
__device__ __forceinline__ void gemv_part_ma(
    float (&res)[NG][G],
    const ulonglong2* const (&Wv)[NG],
    const float* const (&av)[NG], int astride, int j)
{
    constexpr int CH = K2H / 2;
    static_assert(CH % 2 == 0, "chunks must be even");

    u64 acc[NG][G];
#pragma unroll
    for (int ng = 0; ng < NG; ng++)
#pragma unroll
        for (int g = 0; g < G; g++) acc[ng][g] = 0ull;

    ulonglong2 wA[NG], wB[NG];

    auto LD = [&](ulonglong2 (&w)[NG], int c) {
#pragma unroll
        for (int ng = 0; ng < NG; ng++) w[ng] = Wv[ng][c * N + j];
    };
    auto CP = [&](ulonglong2 (&w)[NG], int c) {
#pragma unroll
        for (int ng = 0; ng < NG; ng++) {
#pragma unroll
            for (int g = 0; g < G; g++) {
                ulonglong2 avv = *(const ulonglong2*)(av[ng] + g * astride + 4 * c);
                acc[ng][g] = ffma2(avv.x, w[ng].x, acc[ng][g]);
                acc[ng][g] = ffma2(avv.y, w[ng].y, acc[ng][g]);
            }
        }
    };

    LD(wA, 0);
#pragma unroll 1
    for (int cc = 0; cc < CH / 2; cc++) {
        LD(wB, 2 * cc + 1);
        CP(wA, 2 * cc);
        if (cc + 1 < CH / 2) LD(wA, 2 * cc + 2);
        CP(wB, 2 * cc + 1);
    }

#pragma unroll
    for (int ng = 0; ng < NG; ng++)
#pragma unroll
        for (int g = 0; g < G; g++) res[ng][g] = lanesum(acc[ng][g]);
}

// Decoder dual partial: 2 trajectories x (yt, df), 16 k4 rows, N=128.
__device__ __forceinline__ void gemv_dec_dual(
    float (&ryt)[2], float (&rdf)[2], const ulonglong2* W,
    const float* yt0, const float* yt1,
    const float* df0, const float* df1, int jd)
{
    constexpr int CU = 4, CH = 4;  // 16 k4 rows
    u64 ay0 = 0ull, ay1 = 0ull, ad0 = 0ull, ad1 = 0ull;
    ulonglong2 wA[CU], wB[CU];

    auto LD = [&](ulonglong2 (&w)[CU], int c) {
#pragma unroll
        for (int cu = 0; cu < CU; cu++) w[cu] = W[(c * CU + cu) * 128 + jd];
    };
    auto CP = [&](ulonglong2 (&w)[CU], int c) {
#pragma unroll
        for (int cu = 0; cu < CU; cu++) {
            int k4 = c * CU + cu;
            ulonglong2 vy0 = *(const ulonglong2*)(yt0 + 4 * k4);
            ulonglong2 vy1 = *(const ulonglong2*)(yt1 + 4 * k4);
            ulonglong2 vd0 = *(const ulonglong2*)(df0 + 4 * k4);
            ulonglong2 vd1 = *(const ulonglong2*)(df1 + 4 * k4);
            ay0 = ffma2(vy0.x, w[cu].x, ay0); ay0 = ffma2(vy0.y, w[cu].y, ay0);
            ay1 = ffma2(vy1.x, w[cu].x, ay1); ay1 = ffma2(vy1.y, w[cu].y, ay1);
            ad0 = ffma2(vd0.x, w[cu].x, ad0); ad0 = ffma2(vd0.y, w[cu].y, ad0);
            ad1 = ffma2(vd1.x, w[cu].x, ad1); ad1 = ffma2(vd1.y, w[cu].y, ad1);
        }
    };

    LD(wA, 0);
#pragma unroll 1
    for (int cc = 0; cc < CH / 2; cc++) {
        LD(wB, 2 * cc + 1);
        CP(wA, 2 * cc);
        if (cc + 1 < CH / 2) LD(wA, 2 * cc + 2);
        CP(wB, 2 * cc + 1);
    }
    ryt[0] = lanesum(ay0); ryt[1] = lanesum(ay1);
    rdf[0] = lanesum(ad0); rdf[1] = lanesum(ad1);
}

// ---------------------------------------------------------------------------
// Shared memory layout (dynamic). ~150 KB
// PP slots: 0 = decay-L1 / generic ; 1..3 = gate A (W*yt + W*xh) ; 4..6 = gate B (W*df)
// ---------------------------------------------------------------------------
struct __align__(16) SM {
    float sy [G * 256];
    float syt[G * 256];
    float sdf[G * 256];
    float syc[G * GIN];
    float shh0[G * 256];
    float shh1[G * 256];
    float shh2[G * 256];
    float sdk [G * 256];
    float PP[2][7][256][G];     // intra-CTA quarter partials (both q store)
    float PPd[2][2][128][G];    // decoder intra partials [kq][yt/df]
    float EA[7][256][G];        // cluster exchange, W1 + W3(slot0) + W4(slot1)
    float EB[3][256][G];        // cluster exchange, W2
    float Dl[2][128][G];        // decoder rank-sum, local
    float Dr[2][128][G];        // decoder rank-sum from peer
    float sdt[G], sdecay[G], smask[G], se1[G], se2[G];
    float sred[8][G];
};
#define SMEM_BYTES ((int)sizeof(SM))

__global__ void __cluster_dims__(2, 1, 1) __launch_bounds__(THREADS, 1)
rnn_decay_kernel(
    const float* __restrict__ data, const float* __restrict__ ts,
    const float* __restrict__ ug_b1,  const float* __restrict__ ug_b2,
    const float* __restrict__ ugt_b1, const float* __restrict__ ugt_b2,
    const float* __restrict__ rg_b1,  const float* __restrict__ rg_b2,
    const float* __restrict__ ns_b1,  const float* __restrict__ ns_b2,
    const float* __restrict__ dk_b1,  const float* __restrict__ dk_w2,
    const float* __restrict__ dk_b2,  const float* __restrict__ dec_b,
    float* __restrict__ out)
{
    extern __shared__ __align__(16) char smraw[];
    SM* sm = reinterpret_cast<SM*>(smraw);

    const int tid  = threadIdx.x;        // 0..511
    const int j    = tid & 255;          // output unit
    const int q    = tid >> 8;           // intra-CTA k-quarter select
    const int lane = tid & 31, warp = tid >> 5;
    const uint32_t rank = ctarank();
    const int tb   = (blockIdx.x >> 1) * G;
    const int kqid = (int)rank * 2 + q;  // global K-quarter 0..3

    const uint32_t sb = smem_u32(sm);
    const uint32_t pb = mapa_u32(sb, rank ^ 1u);
    const uint32_t pEA = pb + (uint32_t)offsetof(SM, EA);
    const uint32_t pEB = pb + (uint32_t)offsetof(SM, EB);
    const uint32_t pDr = pb + (uint32_t)offsetof(SM, Dr);

    const ulonglong2* WP = g_wp;

    // K-slice offsets for this quarter
    const int r256 = kqid * 16 * 256;     // 256-row matrices (16 k4/quarter)
    const int a256 = kqid * 64;           // act offset, 256 inputs
    const int r384 = kqid * 24 * 256;     // 384-row matrices (NS1)
    const int a384 = kqid * 96;
    const int rg1y = kqid * 16 * 256;     // gate1 y-rows (k4 0..63)
    const int rg1x = (64 + kqid * 8) * 256; // gate1 xh-rows (k4 64..95)
    const int ag1x = LATENT + kqid * 32;  // xh act offset within syc

    // decoder mapping: sel = (kq, gp); each thread does 2 trajectories
    const int jd = tid & 127, sel = tid >> 7;
    const int gp = (sel & 1) * 2, kq = sel >> 1;

    float* out_prev = out;
    float* out_vol  = out + (size_t)NTRAJ * LATENT;
    float* out_dts  = out + (size_t)NTRAJ * LATENT + (size_t)NTRAJ * NSTEP * DEC_OUT;

    for (int i = tid; i < G * 256; i += THREADS) { sm->sy[i] = 0.f; sm->syt[i] = 0.f; }

    for (int t = 0; t < NTP; t++) {
        CLUSTER_SYNC();   // S0

        // ---- setup: xh, df = y - yt, mask, dt ----
        {
            int g = tid >> 7, jj = tid & 127;
            sm->syc[g * GIN + LATENT + jj] =
                data[((size_t)(tb + g) * NTP + t) * (2 * INPUT) + jj];
        }
        for (int it = tid; it < G * 256; it += THREADS)
            sm->sdf[it] = sm->sy[it] - sm->syt[it];
        if (warp < G) {
            const float* xp = data + ((size_t)(tb + warp) * NTP + t) * (2 * INPUT) + INPUT;
            float s = xp[lane] + xp[lane + 32] + xp[lane + 64] + xp[lane + 96];
#pragma unroll
            for (int off = 16; off; off >>= 1) s += __shfl_xor_sync(0xffffffffu, s, off);
            if (lane == 0) sm->smask[warp] = (s > 0.f) ? 1.f : 0.f;
        }
        if (tid < G && t > 0) {
            float d = ts[(size_t)(tb + tid) * NTP + t] - ts[(size_t)(tb + tid) * NTP + t - 1];
            sm->sdt[tid] = d;
            if (rank == 0)
                out_dts[(size_t)(tb + tid) * NSTEP + (t - 1)] = d;
        }
        __syncthreads();

        // ================= W1: decay L1 + gate1 pre-parts + decoder ========
        {
            // decay layer1 partial (input = y)
            float pdk[1][G];
            const ulonglong2* Wd[1] = { WP + OFF_DK1 + r256 };
            gemv_part<32, 1, 256, 4>(pdk, Wd, sm->sy + a256, 256, j);
            *(float4*)&sm->PP[q][0][j][0] =
                make_float4(pdk[0][0], pdk[0][1], pdk[0][2], pdk[0][3]);

            // gate pre-parts: A = W_y*yt + W_xh*xh ; B = W_y*df
            const int G1OFF[3] = { OFF_UG1, OFF_UGT1, OFF_RG1 };
#pragma unroll
            for (int m = 0; m < 3; m++) {
                float pA[G], pB[G];
                gemv_dual<32, 256, 2>(pA, pB, WP + G1OFF[m] + rg1y,
                                      sm->syt + a256, sm->sdf + a256, 256, j);
                float pX[1][G];
                const ulonglong2* Wx[1] = { WP + G1OFF[m] + rg1x };
                gemv_part<16, 1, 256, 2>(pX, Wx, sm->syc + ag1x, GIN, j);
#pragma unroll
                for (int g = 0; g < G; g++) pA[g] += pX[0][g];
                *(float4*)&sm->PP[q][1 + m][j][0] = make_float4(pA[0], pA[1], pA[2], pA[3]);
                *(float4*)&sm->PP[q][4 + m][j][0] = make_float4(pB[0], pB[1], pB[2], pB[3]);
            }

            // decoder pre-parts: dec*yt, dec*df
            float dyt[2], ddf[2];
            const ulonglong2* Wdc = WP + OFF_DEC + ((int)rank * 32 + kq * 16) * 128;
            int ao = (int)rank * 128 + kq * 64;
            gemv_dec_dual(dyt, ddf, Wdc,
                          sm->syt + (gp + 0) * 256 + ao, sm->syt + (gp + 1) * 256 + ao,
                          sm->sdf + (gp + 0) * 256 + ao, sm->sdf + (gp + 1) * 256 + ao, jd);
            sm->PPd[kq][0][jd][gp + 0] = dyt[0];
            sm->PPd[kq][0][jd][gp + 1] = dyt[1];
            sm->PPd[kq][1][jd][gp + 0] = ddf[0];
            sm->PPd[kq][1][jd][gp + 1] = ddf[1];
        }
        __syncthreads();

        // q0: intra sums -> peer exchange
        if (!q) {
#pragma unroll
            for (int s = 0; s < 7; s++) {
                float4 v0 = *(const float4*)&sm->PP[0][s][j][0];
                float4 v1 = *(const float4*)&sm->PP[1][s][j][0];
                st_peer_f4(pEA + (uint32_t)((s * 256 + j) * G * 4),
                           v0.x + v1.x, v0.y + v1.y, v0.z + v1.z, v0.w + v1.w);
            }
            // decoder rank sums (q0 threads have kq==0; gp0 = tid>>7)
            int gp0 = (tid >> 7) * 2;
#pragma unroll
            for (int a = 0; a < 2; a++) {
                float s0 = sm->PPd[0][a][jd][gp0 + 0] + sm->PPd[1][a][jd][gp0 + 0];
                float s1 = sm->PPd[0][a][jd][gp0 + 1] + sm->PPd[1][a][jd][gp0 + 1];
                sm->Dl[a][jd][gp0 + 0] = s0;
                sm->Dl[a][jd][gp0 + 1] = s1;
                if (rank == 1)
                    st_peer_f2(pDr + (uint32_t)(((a * 128 + jd) * G + gp0) * 4), s0, s1);
            }
        }
        CLUSTER_SYNC();  // CS-A

        // decay combine + relu
        if (!q) {
            float bv = dk_b1[j];
            float4 v0 = *(const float4*)&sm->PP[0][0][j][0];
            float4 v1 = *(const float4*)&sm->PP[1][0][j][0];
            float4 pr = *(const float4*)&sm->EA[0][j][0];
            sm->sdk[0 * 256 + j] = fmaxf(v0.x + v1.x + pr.x + bv, 0.f);
            sm->sdk[1 * 256 + j] = fmaxf(v0.y + v1.y + pr.y + bv, 0.f);
            sm->sdk[2 * 256 + j] = fmaxf(v0.z + v1.z + pr.z + bv, 0.f);
            sm->sdk[3 * 256 + j] = fmaxf(v0.w + v1.w + pr.w + bv, 0.f);
        }
        __syncthreads();
        // decay L2: 256->1 (q0 warps, redundant per rank)
        if (!q) {
            float v[G];
            float w2v = dk_w2[j];
#pragma unroll
            for (int g = 0; g < G; g++) v[g] = sm->sdk[g * 256 + j] * w2v;
#pragma unroll
            for (int off = 16; off; off >>= 1)
#pragma unroll
                for (int g = 0; g < G; g++) v[g] += __shfl_xor_sync(0xffffffffu, v[g], off);
            if (lane == 0)
#pragma unroll
                for (int g = 0; g < G; g++) sm->sred[warp][g] = v[g];
        }
        __syncthreads();
        if (tid < G) {
            float s = dk_b2[0];
#pragma unroll
            for (int w = 0; w < 8; w++) s += sm->sred[w][tid];
            float dec = fmaxf(s, 0.f);
            float d = dec * sm->sdt[tid];
            sm->sdecay[tid] = dec;
            sm->se1[tid] = __expf(-0.5f * d);
            sm->se2[tid] = __expf(-d);
        }
        __syncthreads();

        // combines: gates (q0) ; vol + y_end (q1)
        if (!q) {
            const float* B1[3] = { ug_b1, ugt_b1, rg_b1 };
            float* SH[3] = { sm->shh0, sm->shh1, sm->shh2 };
#pragma unroll
            for (int m = 0; m < 3; m++) {
                float bv = B1[m][j];
                float4 a0 = *(const float4*)&sm->PP[0][1 + m][j][0];
                float4 a1 = *(const float4*)&sm->PP[1][1 + m][j][0];
                float4 ap = *(const float4*)&sm->EA[1 + m][j][0];
                float4 b0 = *(const float4*)&sm->PP[0][4 + m][j][0];
                float4 b1v = *(const float4*)&sm->PP[1][4 + m][j][0];
                float4 bp = *(const float4*)&sm->EA[4 + m][j][0];
                float Aa[G] = { a0.x + a1.x + ap.x, a0.y + a1.y + ap.y,
                                a0.z + a1.z + ap.z, a0.w + a1.w + ap.w };
                float Bb[G] = { b0.x + b1v.x + bp.x, b0.y + b1v.y + bp.y,
                                b0.z + b1v.z + bp.z, b0.w + b1v.w + bp.w };
#pragma unroll
                for (int g = 0; g < G; g++)
                    SH[m][g * 256 + j] = tanhf(Aa[g] + sm->se2[g] * Bb[g] + bv);
            }
        } else {
            int i = tid - 256;
            if (t > 0 && rank == 0) {
                int jd2 = i & 127, gp2 = (i >> 7) * 2;
                float bv = dec_b[jd2];
#pragma unroll
                for (int i2 = 0; i2 < 2; i2++) {
                    int g = gp2 + i2;
                    float s1 = 0.5f * (1.f + sm->se1[g]);
                    float v = (sm->Dl[0][jd2][g] + sm->Dr[0][jd2][g])
                            + s1 * (sm->Dl[1][jd2][g] + sm->Dr[1][jd2][g]) + bv;
                    out_vol[((size_t)(tb + g) * NSTEP + (t - 1)) * DEC_OUT + jd2] = v;
                }
            }
            // y_end = yt + e2*df  ->  sy, syc head
            for (int it = i; it < G * 256; it += 256) {
                int g = it >> 8, jj = it & 255;
                float ye = sm->syt[g * 256 + jj] + sm->se2[g] * sm->sdf[g * 256 + jj];
                sm->sy[g * 256 + jj] = ye;
                sm->syc[g * GIN + jj] = ye;
            }
        }
        __syncthreads();

        // ================= W2: gate layer 2 x3 ============================
        float u[G], ut[G];   // valid on q0 after CS-B
        {
            const ulonglong2* Wg[3] = { WP + OFF_UG2  + r256,
                                        WP + OFF_UGT2 + r256,
                                        WP + OFF_RG2  + r256 };
            const float* av[3] = { sm->shh0 + a256, sm->shh1 + a256, sm->shh2 + a256 };
            float p[3][G];
            gemv_part_ma<32, 3, 256>(p, Wg, av, 256, j);
#pragma unroll
            for (int ng = 0; ng < 3; ng++)
                *(float4*)&sm->PP[q][ng][j][0] =
                    make_float4(p[ng][0], p[ng][1], p[ng][2], p[ng][3]);
            __syncthreads();
            if (!q) {
#pragma unroll
                for (int ng = 0; ng < 3; ng++) {
                    float4 v0 = *(const float4*)&sm->PP[0][ng][j][0];
                    float4 v1 = *(const float4*)&sm->PP[1][ng][j][0];
                    st_peer_f4(pEB + (uint32_t)((ng * 256 + j) * G * 4),
                               v0.x + v1.x, v0.y + v1.y, v0.z + v1.z, v0.w + v1.w);
                }
            }
            CLUSTER_SYNC();  // CS-B
            if (!q) {
                float4 v0 = *(const float4*)&sm->PP[0][0][j][0];
                float4 v1 = *(const float4*)&sm->PP[1][0][j][0];
                float4 pr = *(const float4*)&sm->EB[0][j][0];
                float b0 = ug_b2[j];
                u[0] = sigmoid_fast(v0.x + v1.x + pr.x + b0);
                u[1] = sigmoid_fast(v0.y + v1.y + pr.y + b0);
                u[2] = sigmoid_fast(v0.z + v1.z + pr.z + b0);
                u[3] = sigmoid_fast(v0.w + v1.w + pr.w + b0);
                v0 = *(const float4*)&sm->PP[0][1][j][0];
                v1 = *(const float4*)&sm->PP[1][1][j][0];
                pr = *(const float4*)&sm->EB[1][j][0];
                float b1v = ugt_b2[j];
                ut[0] = sigmoid_fast(v0.x + v1.x + pr.x + b1v);
                ut[1] = sigmoid_fast(v0.y + v1.y + pr.y + b1v);
                ut[2] = sigmoid_fast(v0.z + v1.z + pr.z + b1v);
                ut[3] = sigmoid_fast(v0.w + v1.w + pr.w + b1v);
                v0 = *(const float4*)&sm->PP[0][2][j][0];
                v1 = *(const float4*)&sm->PP[1][2][j][0];
                pr = *(const float4*)&sm->EB[2][j][0];
                float b2 = rg_b2[j];
                sm->syc[0 * GIN + j] *= sigmoid_fast(v0.x + v1.x + pr.x + b2);
                sm->syc[1 * GIN + j] *= sigmoid_fast(v0.y + v1.y + pr.y + b2);
                sm->syc[2 * GIN + j] *= sigmoid_fast(v0.z + v1.z + pr.z + b2);
                sm->syc[3 * GIN + j] *= sigmoid_fast(v0.w + v1.w + pr.w + b2);
            }
            __syncthreads();
        }

        // ================= W3: new_state layer 1 (384->256) ===============
        {
            const ulonglong2* Wg[1] = { WP + OFF_NS1 + r384 };
            float p[1][G];
            gemv_part<48, 1, 256, 4>(p, Wg, sm->syc + a384, GIN, j);
            *(float4*)&sm->PP[q][0][j][0] = make_float4(p[0][0], p[0][1], p[0][2], p[0][3]);
            __syncthreads();
            if (!q) {
                float4 v0 = *(const float4*)&sm->PP[0][0][j][0];
                float4 v1 = *(const float4*)&sm->PP[1][0][j][0];
                st_peer_f4(pEA + (uint32_t)(j * G * 4),
                           v0.x + v1.x, v0.y + v1.y, v0.z + v1.z, v0.w + v1.w);
            }
            CLUSTER_SYNC();  // CS-C
            if (!q) {
                float bv = ns_b1[j];
                float4 v0 = *(const float4*)&sm->PP[0][0][j][0];
                float4 v1 = *(const float4*)&sm->PP[1][0][j][0];
                float4 pr = *(const float4*)&sm->EA[0][j][0];
                sm->shh0[0 * 256 + j] = tanhf(v0.x + v1.x + pr.x + bv);
                sm->shh0[1 * 256 + j] = tanhf(v0.y + v1.y + pr.y + bv);
                sm->shh0[2 * 256 + j] = tanhf(v0.z + v1.z + pr.z + bv);
                sm->shh0[3 * 256 + j] = tanhf(v0.w + v1.w + pr.w + bv);
            }
            __syncthreads();
        }

        // ================= W4: new_state layer 2 + masked update ==========
        {
            const ulonglong2* Wg[1] = { WP + OFF_NS2 + r256 };
            float p[1][G];
            gemv_part<32, 1, 256, 4>(p, Wg, sm->shh0 + a256, 256, j);
            *(float4*)&sm->PP[q][1][j][0] = make_float4(p[0][0], p[0][1], p[0][2], p[0][3]);
            __syncthreads();
            if (!q) {
                float4 v0 = *(const float4*)&sm->PP[0][1][j][0];
                float4 v1 = *(const float4*)&sm->PP[1][1][j][0];
                st_peer_f4(pEA + (uint32_t)((1 * 256 + j) * G * 4),
                           v0.x + v1.x, v0.y + v1.y, v0.z + v1.z, v0.w + v1.w);
            }
            CLUSTER_SYNC();  // CS-D
            if (!q) {
                float bv = ns_b2[j];
                float4 v0 = *(const float4*)&sm->PP[0][1][j][0];
                float4 v1 = *(const float4*)&sm->PP[1][1][j][0];
                float4 pr = *(const float4*)&sm->EA[1][j][0];
                float nsvv[G] = { v0.x + v1.x + pr.x + bv, v0.y + v1.y + pr.y + bv,
                                  v0.z + v1.z + pr.z + bv, v0.w + v1.w + pr.w + bv };
#pragma unroll
                for (int g = 0; g < G; g++) {
                    float m    = sm->smask[g];
                    float yend = sm->sy[g * 256 + j], ytv = sm->syt[g * 256 + j];
                    float ny   = (1.f - u[g])  * nsvv[g] + u[g]  * yend;
                    float nyt  = (1.f - ut[g]) * nsvv[g] + ut[g] * ytv;
                    sm->sy [g * 256 + j] = m * ny  + (1.f - m) * yend;
                    sm->syt[g * 256 + j] = m * nyt + (1.f - m) * ytv;
                }
            }
        }
        // next S0 publishes state and protects buffer reuse
    }

    CLUSTER_SYNC();
    if (rank == 0 && !q) {
#pragma unroll
        for (int g = 0; g < G; g++)
            out_prev[(size_t)(tb + g) * LATENT + j] = sm->sy[g * 256 + j];
    }
}

extern "C" void kernel_launch(void* const* d_in, const int* in_sizes, int n_in,
                              void* d_out, int out_size) {
    const float* data   = (const float*)d_in[0];
    const float* ts     = (const float*)d_in[1];
    const float* ug_w1  = (const float*)d_in[2];
    const float* ug_b1  = (const float*)d_in[3];
    const float* ug_w2  = (const float*)d_in[4];
    const float* ug_b2  = (const float*)d_in[5];
    const float* ugt_w1 = (const float*)d_in[6];
    const float* ugt_b1 = (const float*)d_in[7];
    const float* ugt_w2 = (const float*)d_in[8];
    const float* ugt_b2 = (const float*)d_in[9];
    const float* rg_w1  = (const float*)d_in[10];
    const float* rg_b1  = (const float*)d_in[11];
    const float* rg_w2  = (const float*)d_in[12];
    const float* rg_b2  = (const float*)d_in[13];
    // d_in[14..17] = rgt_* : unused by the reference
    const float* ns_w1  = (const float*)d_in[18];
    const float* ns_b1  = (const float*)d_in[19];
    const float* ns_w2  = (const float*)d_in[20];
    const float* ns_b2  = (const float*)d_in[21];
    const float* dk_w1  = (const float*)d_in[22];
    const float* dk_b1  = (const float*)d_in[23];
    const float* dk_w2  = (const float*)d_in[24];
    const float* dk_b2  = (const float*)d_in[25];
    const float* dec_w  = (const float*)d_in[26];
    const float* dec_b  = (const float*)d_in[27];

    cudaFuncSetAttribute(rnn_decay_kernel,
                         cudaFuncAttributeMaxDynamicSharedMemorySize, SMEM_BYTES);

    pack_kernel<<<(WP_TOTAL + 255) / 256, 256>>>(
        ug_w1, ugt_w1, rg_w1, ns_w1, ug_w2, ugt_w2, rg_w2, ns_w2, dk_w1, dec_w);

    rnn_decay_kernel<<<NBLK, THREADS, SMEM_BYTES>>>(
        data, ts,
        ug_b1, ug_b2, ugt_b1, ugt_b2, rg_b1, rg_b2,
        ns_b1, ns_b2, dk_b1, dk_w2, dk_b2, dec_b,
        (float*)d_out);
}

// round 12
// speedup vs baseline: 1.9804x; 1.5126x over previous
#include <cuda_runtime.h>
#include <cuda_bf16.h>
#include <math.h>
#include <stdint.h>
#include <stddef.h>

#define NTRAJ  256
#define NTP    512
#define LATENT 256
#define INPUT  128
#define NUNITS 256
#define GIN    (LATENT + INPUT)   // 384
#define DEC_OUT 128
#define NSTEP  (NTP - 1)          // 511

#define G       4                 // trajectories per cluster
#define NCLU    (NTRAJ / G)       // 64 clusters
#define NBLK    (NCLU * 2)        // 128 CTAs (2 per cluster, N-split)
#define THREADS 512               // intra-CTA split-K x4 (kq groups)

typedef unsigned long long u64;

union F2U { float2 f; u64 u; };

__device__ __forceinline__ u64 ffma2(u64 a, u64 b, u64 c) {
    u64 d;
    asm("fma.rn.f32x2 %0, %1, %2, %3;" : "=l"(d) : "l"(a), "l"(b), "l"(c));
    return d;
}
__device__ __forceinline__ float lanesum(u64 v) {
    F2U r; r.u = v; return r.f.x + r.f.y;
}
__device__ __forceinline__ float sigmoid_fast(float x) {
    return __fdividef(1.f, 1.f + __expf(-x));
}
__device__ __forceinline__ uint32_t smem_u32(const void* p) {
    uint32_t a;
    asm("{ .reg .u64 t; cvta.to.shared.u64 t, %1; cvt.u32.u64 %0, t; }" : "=r"(a) : "l"(p));
    return a;
}
__device__ __forceinline__ uint32_t ctarank() {
    uint32_t r; asm("mov.u32 %0, %%cluster_ctarank;" : "=r"(r)); return r;
}
__device__ __forceinline__ uint32_t mapa_u32(uint32_t addr, uint32_t rank) {
    uint32_t r;
    asm("mapa.shared::cluster.u32 %0, %1, %2;" : "=r"(r) : "r"(addr), "r"(rank));
    return r;
}
__device__ __forceinline__ void st_peer_f1(uint32_t dst, float v) {
    asm volatile("st.shared::cluster.u32 [%0], %1;" :: "r"(dst), "f"(v) : "memory");
}
#define CLUSTER_SYNC() do { \
    asm volatile("barrier.cluster.arrive.aligned;" ::: "memory"); \
    asm volatile("barrier.cluster.wait.aligned;"   ::: "memory"); \
} while (0)

// ---------------------------------------------------------------------------
// Packed weights: float4 along k: W4[k4][j] = W[4k4..4k4+3][j], as ulonglong2.
// ---------------------------------------------------------------------------
#define SZ_M384 (96 * 256)
#define SZ_M256 (64 * 256)
#define SZ_DEC  (64 * 128)
#define OFF_UG1  0
#define OFF_UGT1 (OFF_UG1  + SZ_M384)
#define OFF_RG1  (OFF_UGT1 + SZ_M384)
#define OFF_NS1  (OFF_RG1  + SZ_M384)
#define OFF_UG2  (OFF_NS1  + SZ_M384)
#define OFF_UGT2 (OFF_UG2  + SZ_M256)
#define OFF_RG2  (OFF_UGT2 + SZ_M256)
#define OFF_NS2  (OFF_RG2  + SZ_M256)
#define OFF_DK1  (OFF_NS2  + SZ_M256)
#define OFF_DEC  (OFF_DK1  + SZ_M256)
#define WP_TOTAL (OFF_DEC  + SZ_DEC)

__device__ ulonglong2 g_wp[WP_TOTAL];

__global__ void pack_kernel(
    const float* ug1, const float* ugt1, const float* rg1, const float* ns1,
    const float* ug2, const float* ugt2, const float* rg2, const float* ns2,
    const float* dk1, const float* decw)
{
    const float* srcs[10] = {ug1, ugt1, rg1, ns1, ug2, ugt2, rg2, ns2, dk1, decw};
    const int offs[11] = {OFF_UG1, OFF_UGT1, OFF_RG1, OFF_NS1, OFF_UG2, OFF_UGT2,
                          OFF_RG2, OFF_NS2, OFF_DK1, OFF_DEC, WP_TOTAL};
    const int Ns[10] = {256,256,256,256,256,256,256,256,256,128};

    int idx = blockIdx.x * blockDim.x + threadIdx.x;
    if (idx >= WP_TOTAL) return;
    int m = 0;
    while (idx >= offs[m + 1]) m++;
    int local = idx - offs[m];
    int N = Ns[m];
    int k4 = local / N, j = local % N;
    const float* S = srcs[m];
    F2U lo, hi;
    lo.f = make_float2(S[(4 * k4 + 0) * N + j], S[(4 * k4 + 1) * N + j]);
    hi.f = make_float2(S[(4 * k4 + 2) * N + j], S[(4 * k4 + 3) * N + j]);
    g_wp[idx] = make_ulonglong2(lo.u, hi.u);
}

// ---------------------------------------------------------------------------
// Partial packed GEMV (quarter-K), shared activation. A/B register buffer.
// Identical inner loop to the proven R9 template.
// ---------------------------------------------------------------------------
template <int K2H, int NG, int N, int CU>
__device__ __forceinline__ void gemv_part(
    float (&res)[NG][G],
    const ulonglong2* const (&Wv)[NG],
    const float* act, int astride, int j)
{
    constexpr int K4 = K2H / 2;
    constexpr int CH = K4 / CU;
    static_assert(CH % 2 == 0, "chunks must be even");

    u64 acc[NG][G];
#pragma unroll
    for (int ng = 0; ng < NG; ng++)
#pragma unroll
        for (int g = 0; g < G; g++) acc[ng][g] = 0ull;

    ulonglong2 wA[NG][CU], wB[NG][CU];

    auto LD = [&](ulonglong2 (&w)[NG][CU], int c) {
#pragma unroll
        for (int ng = 0; ng < NG; ng++)
#pragma unroll
            for (int cu = 0; cu < CU; cu++)
                w[ng][cu] = Wv[ng][(c * CU + cu) * N + j];
    };
    auto CP = [&](ulonglong2 (&w)[NG][CU], int c) {
#pragma unroll
        for (int cu = 0; cu < CU; cu++) {
            int k4 = c * CU + cu;
#pragma unroll
            for (int g = 0; g < G; g++) {
                ulonglong2 av = *(const ulonglong2*)(act + g * astride + 4 * k4);
#pragma unroll
                for (int ng = 0; ng < NG; ng++) {
                    acc[ng][g] = ffma2(av.x, w[ng][cu].x, acc[ng][g]);
                    acc[ng][g] = ffma2(av.y, w[ng][cu].y, acc[ng][g]);
                }
            }
        }
    };

    LD(wA, 0);
#pragma unroll 1
    for (int cc = 0; cc < CH / 2; cc++) {
        LD(wB, 2 * cc + 1);
        CP(wA, 2 * cc);
        if (cc + 1 < CH / 2) LD(wA, 2 * cc + 2);
        CP(wB, 2 * cc + 1);
    }

#pragma unroll
    for (int ng = 0; ng < NG; ng++)
#pragma unroll
        for (int g = 0; g < G; g++) res[ng][g] = lanesum(acc[ng][g]);
}

// Per-matrix-activation variant (gate layer 2), CU=1.
template <int K2H, int NG, int N>
__device__ __forceinline__ void gemv_part_ma(
    float (&res)[NG][G],
    const ulonglong2* const (&Wv)[NG],
    const float* const (&av)[NG], int astride, int j)
{
    constexpr int CH = K2H / 2;
    static_assert(CH % 2 == 0, "chunks must be even");

    u64 acc[NG][G];
#pragma unroll
    for (int ng = 0; ng < NG; ng++)
#pragma unroll
        for (int g = 0; g < G; g++) acc[ng][g] = 0ull;

    ulonglong2 wA[NG], wB[NG];

    auto LD = [&](ulonglong2 (&w)[NG], int c) {
#pragma unroll
        for (int ng = 0; ng < NG; ng++) w[ng] = Wv[ng][c * N + j];
    };
    auto CP = [&](ulonglong2 (&w)[NG], int c) {
#pragma unroll
        for (int ng = 0; ng < NG; ng++) {
#pragma unroll
            for (int g = 0; g < G; g++) {
                ulonglong2 avv = *(const ulonglong2*)(av[ng] + g * astride + 4 * c);
                acc[ng][g] = ffma2(avv.x, w[ng].x, acc[ng][g]);
                acc[ng][g] = ffma2(avv.y, w[ng].y, acc[ng][g]);
            }
        }
    };

    LD(wA, 0);
#pragma unroll 1
    for (int cc = 0; cc < CH / 2; cc++) {
        LD(wB, 2 * cc + 1);
        CP(wA, 2 * cc);
        if (cc + 1 < CH / 2) LD(wA, 2 * cc + 2);
        CP(wB, 2 * cc + 1);
    }

#pragma unroll
    for (int ng = 0; ng < NG; ng++)
#pragma unroll
        for (int g = 0; g < G; g++) res[ng][g] = lanesum(acc[ng][g]);
}

// Decoder: one (output jd, trajectory) pair, half-K (32 k4 rows), N=128.
__device__ __forceinline__ float gemv_dec1(
    const ulonglong2* W, const float* act, int jd)
{
    constexpr int CU = 4, CH = 8;  // 32 k4 rows
    u64 acc = 0ull;
    ulonglong2 wA[CU], wB[CU];

    auto LD = [&](ulonglong2 (&w)[CU], int c) {
#pragma unroll
        for (int cu = 0; cu < CU; cu++) w[cu] = W[(c * CU + cu) * 128 + jd];
    };
    auto CP = [&](ulonglong2 (&w)[CU], int c) {
#pragma unroll
        for (int cu = 0; cu < CU; cu++) {
            int k4 = c * CU + cu;
            ulonglong2 a = *(const ulonglong2*)(act + 4 * k4);
            acc = ffma2(a.x, w[cu].x, acc);
            acc = ffma2(a.y, w[cu].y, acc);
        }
    };

    LD(wA, 0);
#pragma unroll 1
    for (int cc = 0; cc < CH / 2; cc++) {
        LD(wB, 2 * cc + 1);
        CP(wA, 2 * cc);
        if (cc + 1 < CH / 2) LD(wA, 2 * cc + 2);
        CP(wB, 2 * cc + 1);
    }
    return lanesum(acc);
}

// ---------------------------------------------------------------------------
// Shared memory layout (dynamic). ~50 KB
// ---------------------------------------------------------------------------
struct __align__(16) SM {
    float sy  [G * 256];        // full in both CTAs
    float syt [G * 256];        // full in both CTAs
    float syc [G * GIN];        // full in both CTAs
    float shh0[G * 256];
    float shh1[G * 256];
    float shh2[G * 256];
    float smean[G * 256];       // mean_ydec (local, replicated)
    float Q[3][3][128][G];      // intra-CTA K-quarter partials (kq 0..2 write)
    float Pd[64][G];            // decoder kh1 partial
    float Dl[G], Dr[G];         // decay-L2 half sums (local / from peer)
    float sdt[G], smask[G], se1[G], se2[G];
    float sred[4][G];
};
#define SMEM_BYTES ((int)sizeof(SM))

__global__ void __cluster_dims__(2, 1, 1) __launch_bounds__(THREADS, 1)
rnn_decay_kernel(
    const float* __restrict__ data, const float* __restrict__ ts,
    const float* __restrict__ ug_b1,  const float* __restrict__ ug_b2,
    const float* __restrict__ ugt_b1, const float* __restrict__ ugt_b2,
    const float* __restrict__ rg_b1,  const float* __restrict__ rg_b2,
    const float* __restrict__ ns_b1,  const float* __restrict__ ns_b2,
    const float* __restrict__ dk_b1,  const float* __restrict__ dk_w2,
    const float* __restrict__ dk_b2,  const float* __restrict__ dec_b,
    float* __restrict__ out)
{
    extern __shared__ __align__(16) char smraw[];
    SM* sm = reinterpret_cast<SM*>(smraw);

    const int tid  = threadIdx.x;        // 0..511
    const int jloc = tid & 127;          // output column within this CTA's half
    const int kq   = tid >> 7;           // K-quarter 0..3
    const int lane = tid & 31, warp = tid >> 5;
    const uint32_t rank = ctarank();     // N-half owned by this CTA
    const int tb   = (blockIdx.x >> 1) * G;
    const int jglob = (int)rank * 128 + jloc;   // global output column

    const uint32_t sb = smem_u32(sm);
    const uint32_t pb = mapa_u32(sb, rank ^ 1u);
    const uint32_t pSy   = pb + (uint32_t)offsetof(SM, sy);
    const uint32_t pSyt  = pb + (uint32_t)offsetof(SM, syt);
    const uint32_t pSyc  = pb + (uint32_t)offsetof(SM, syc);
    const uint32_t pShh0 = pb + (uint32_t)offsetof(SM, shh0);
    const uint32_t pShh1 = pb + (uint32_t)offsetof(SM, shh1);
    const uint32_t pShh2 = pb + (uint32_t)offsetof(SM, shh2);
    const uint32_t pDr   = pb + (uint32_t)offsetof(SM, Dr);

    const ulonglong2* WP = g_wp;

    // K-quarter offsets (full-K matrices, quarter per kq)
    const int r256q = kq * 16 * 256;   // 256-row matrices: 16 k4 per quarter
    const int a256q = kq * 64;
    const int r384q = kq * 24 * 256;   // 384-row matrices: 24 k4 per quarter
    const int a384q = kq * 96;

    // decoder mapping: (jd, gd, kh); rank owns decoder columns [rank*64, +64)
    const int jd = tid & 63, gd = (tid >> 6) & 3, kh = tid >> 8;
    const int jdglob = (int)rank * 64 + jd;

    float* out_prev = out;
    float* out_vol  = out + (size_t)NTRAJ * LATENT;
    float* out_dts  = out + (size_t)NTRAJ * LATENT + (size_t)NTRAJ * NSTEP * DEC_OUT;

    for (int i = tid; i < G * 256; i += THREADS) { sm->sy[i] = 0.f; sm->syt[i] = 0.f; }

    for (int t = 0; t < NTP; t++) {
        CLUSTER_SYNC();   // S0: state exchange visible; buffer reuse protected

        // ---- setup: xh -> syc tail (both CTAs, full), mask, dt ----
        {
            int g = tid >> 7, jj = tid & 127;
            sm->syc[g * GIN + LATENT + jj] =
                data[((size_t)(tb + g) * NTP + t) * (2 * INPUT) + jj];
        }
        if (warp < G) {
            const float* xp = data + ((size_t)(tb + warp) * NTP + t) * (2 * INPUT) + INPUT;
            float s = xp[lane] + xp[lane + 32] + xp[lane + 64] + xp[lane + 96];
#pragma unroll
            for (int off = 16; off; off >>= 1) s += __shfl_xor_sync(0xffffffffu, s, off);
            if (lane == 0) sm->smask[warp] = (s > 0.f) ? 1.f : 0.f;
        }
        if (tid < G && t > 0) {
            float d = ts[(size_t)(tb + tid) * NTP + t] - ts[(size_t)(tb + tid) * NTP + t - 1];
            sm->sdt[tid] = d;
            if (rank == 0)
                out_dts[(size_t)(tb + tid) * NSTEP + (t - 1)] = d;
        }
        __syncthreads();

        float u[G], ut[G];   // live in kq3 threads after gate2 combine
        float pdec = 0.f;    // decoder own partial (kh0 finalizes)

        if (t > 0) {
            // ---- decay layer1 (own N-half, full K via kq quarters) ----
            {
                const ulonglong2* Wd[1] = { WP + OFF_DK1 + r256q };
                float p[1][G];
                gemv_part<32, 1, 256, 4>(p, Wd, sm->sy + a256q, 256, jglob);
                if (kq != 3)
                    *(float4*)&sm->Q[0][kq][jloc][0] =
                        make_float4(p[0][0], p[0][1], p[0][2], p[0][3]);
                __syncthreads();
                if (kq == 3) {
                    float bv = dk_b1[jglob];
                    float w2v = dk_w2[jglob];
                    float4 q0 = *(const float4*)&sm->Q[0][0][jloc][0];
                    float4 q1 = *(const float4*)&sm->Q[0][1][jloc][0];
                    float4 q2 = *(const float4*)&sm->Q[0][2][jloc][0];
                    float v[G];
                    v[0] = fmaxf(p[0][0] + q0.x + q1.x + q2.x + bv, 0.f) * w2v;
                    v[1] = fmaxf(p[0][1] + q0.y + q1.y + q2.y + bv, 0.f) * w2v;
                    v[2] = fmaxf(p[0][2] + q0.z + q1.z + q2.z + bv, 0.f) * w2v;
                    v[3] = fmaxf(p[0][3] + q0.w + q1.w + q2.w + bv, 0.f) * w2v;
#pragma unroll
                    for (int off = 16; off; off >>= 1)
#pragma unroll
                        for (int g = 0; g < G; g++)
                            v[g] += __shfl_xor_sync(0xffffffffu, v[g], off);
                    if (lane == 0)
#pragma unroll
                        for (int g = 0; g < G; g++) sm->sred[warp & 3][g] = v[g];
                }
                __syncthreads();
                if (tid < G) {
                    float s = sm->sred[0][tid] + sm->sred[1][tid]
                            + sm->sred[2][tid] + sm->sred[3][tid];
                    sm->Dl[tid] = s;
                    st_peer_f1(pDr + (uint32_t)tid * 4u, s);
                }
            }
            CLUSTER_SYNC();  // CS1
            if (tid < G) {
                float dec = fmaxf(sm->Dl[tid] + sm->Dr[tid] + dk_b2[0], 0.f);
                float d = dec * sm->sdt[tid];
                sm->se1[tid] = __expf(-0.5f * d);
                sm->se2[tid] = __expf(-d);
            }
            __syncthreads();

            // ---- elementwise decay (replicated in both CTAs) ----
            for (int it = tid; it < G * 256; it += THREADS) {
                int g = it >> 8, jj = it & 255;
                float yv = sm->sy[g * 256 + jj], ytv = sm->syt[g * 256 + jj];
                float df = yv - ytv;
                sm->smean[g * 256 + jj] = ytv + df * (0.5f * (1.f + sm->se1[g]));
                float ye = ytv + df * sm->se2[g];
                sm->sy[g * 256 + jj] = ye;
                sm->syc[g * GIN + jj] = ye;
            }
            __syncthreads();

            // ---- decoder partial (own 64 columns, half-K per kh) ----
            {
                const ulonglong2* Wd = WP + OFF_DEC + kh * 32 * 128;
                pdec = gemv_dec1(Wd, sm->smean + gd * 256 + kh * 128, jdglob);
                if (kh) sm->Pd[jd][gd] = pdec;
            }
        } else {
            for (int it = tid; it < G * 256; it += THREADS) {
                int g = it >> 8, jj = it & 255;
                sm->syc[g * GIN + jj] = 0.f;
            }
            __syncthreads();
        }

        // ---- gate layer1: ug/ugt/rg fused (384->own 128 cols) ----
        {
            const ulonglong2* Wg[3] = { WP + OFF_UG1  + r384q,
                                        WP + OFF_UGT1 + r384q,
                                        WP + OFF_RG1  + r384q };
            float p[3][G];
            gemv_part<48, 3, 256, 1>(p, Wg, sm->syc + a384q, GIN, jglob);
            if (kq != 3) {
#pragma unroll
                for (int m = 0; m < 3; m++)
                    *(float4*)&sm->Q[m][kq][jloc][0] =
                        make_float4(p[m][0], p[m][1], p[m][2], p[m][3]);
            }
            __syncthreads();   // also publishes Pd
            if (kq == 3) {
                const float* B1[3] = { ug_b1, ugt_b1, rg_b1 };
                float* SH[3] = { sm->shh0, sm->shh1, sm->shh2 };
                const uint32_t PSH[3] = { pShh0, pShh1, pShh2 };
#pragma unroll
                for (int m = 0; m < 3; m++) {
                    float bv = B1[m][jglob];
                    float4 q0 = *(const float4*)&sm->Q[m][0][jloc][0];
                    float4 q1 = *(const float4*)&sm->Q[m][1][jloc][0];
                    float4 q2 = *(const float4*)&sm->Q[m][2][jloc][0];
                    float vv[G] = { p[m][0] + q0.x + q1.x + q2.x + bv,
                                    p[m][1] + q0.y + q1.y + q2.y + bv,
                                    p[m][2] + q0.z + q1.z + q2.z + bv,
                                    p[m][3] + q0.w + q1.w + q2.w + bv };
#pragma unroll
                    for (int g = 0; g < G; g++) {
                        float a = tanhf(vv[g]);
                        int idx = g * 256 + jglob;
                        SH[m][idx] = a;
                        st_peer_f1(PSH[m] + (uint32_t)idx * 4u, a);
                    }
                }
            } else if (t > 0 && kh == 0) {
                // decoder finalize -> global (own 64 columns)
                float v = pdec + sm->Pd[jd][gd] + dec_b[jdglob];
                out_vol[((size_t)(tb + gd) * NSTEP + (t - 1)) * DEC_OUT + jdglob] = v;
            }
        }
        CLUSTER_SYNC();  // CS2

        // ---- gate layer2 x3 (256->own 128 cols), per-matrix acts ----
        {
            const ulonglong2* Wg[3] = { WP + OFF_UG2  + r256q,
                                        WP + OFF_UGT2 + r256q,
                                        WP + OFF_RG2  + r256q };
            const float* av[3] = { sm->shh0 + a256q, sm->shh1 + a256q, sm->shh2 + a256q };
            float p[3][G];
            gemv_part_ma<32, 3, 256>(p, Wg, av, 256, jglob);
            if (kq != 3) {
#pragma unroll
                for (int m = 0; m < 3; m++)
                    *(float4*)&sm->Q[m][kq][jloc][0] =
                        make_float4(p[m][0], p[m][1], p[m][2], p[m][3]);
            }
            __syncthreads();
            if (kq == 3) {
                float b0 = ug_b2[jglob], b1 = ugt_b2[jglob], b2 = rg_b2[jglob];
                float4 q0, q1, q2;
                q0 = *(const float4*)&sm->Q[0][0][jloc][0];
                q1 = *(const float4*)&sm->Q[0][1][jloc][0];
                q2 = *(const float4*)&sm->Q[0][2][jloc][0];
                u[0] = sigmoid_fast(p[0][0] + q0.x + q1.x + q2.x + b0);
                u[1] = sigmoid_fast(p[0][1] + q0.y + q1.y + q2.y + b0);
                u[2] = sigmoid_fast(p[0][2] + q0.z + q1.z + q2.z + b0);
                u[3] = sigmoid_fast(p[0][3] + q0.w + q1.w + q2.w + b0);
                q0 = *(const float4*)&sm->Q[1][0][jloc][0];
                q1 = *(const float4*)&sm->Q[1][1][jloc][0];
                q2 = *(const float4*)&sm->Q[1][2][jloc][0];
                ut[0] = sigmoid_fast(p[1][0] + q0.x + q1.x + q2.x + b1);
                ut[1] = sigmoid_fast(p[1][1] + q0.y + q1.y + q2.y + b1);
                ut[2] = sigmoid_fast(p[1][2] + q0.z + q1.z + q2.z + b1);
                ut[3] = sigmoid_fast(p[1][3] + q0.w + q1.w + q2.w + b1);
                q0 = *(const float4*)&sm->Q[2][0][jloc][0];
                q1 = *(const float4*)&sm->Q[2][1][jloc][0];
                q2 = *(const float4*)&sm->Q[2][2][jloc][0];
                float rr[G] = { sigmoid_fast(p[2][0] + q0.x + q1.x + q2.x + b2),
                                sigmoid_fast(p[2][1] + q0.y + q1.y + q2.y + b2),
                                sigmoid_fast(p[2][2] + q0.z + q1.z + q2.z + b2),
                                sigmoid_fast(p[2][3] + q0.w + q1.w + q2.w + b2) };
#pragma unroll
                for (int g = 0; g < G; g++) {
                    int idx = g * GIN + jglob;
                    float v = sm->syc[idx] * rr[g];
                    sm->syc[idx] = v;
                    st_peer_f1(pSyc + (uint32_t)idx * 4u, v);
                }
            }
        }
        CLUSTER_SYNC();  // CS3

        // ---- new_state layer1 (384->own 128 cols) ----
        {
            const ulonglong2* Wg[1] = { WP + OFF_NS1 + r384q };
            float p[1][G];
            gemv_part<48, 1, 256, 4>(p, Wg, sm->syc + a384q, GIN, jglob);
            if (kq != 3)
                *(float4*)&sm->Q[0][kq][jloc][0] =
                    make_float4(p[0][0], p[0][1], p[0][2], p[0][3]);
            __syncthreads();
            if (kq == 3) {
                float bv = ns_b1[jglob];
                float4 q0 = *(const float4*)&sm->Q[0][0][jloc][0];
                float4 q1 = *(const float4*)&sm->Q[0][1][jloc][0];
                float4 q2 = *(const float4*)&sm->Q[0][2][jloc][0];
                float vv[G] = { p[0][0] + q0.x + q1.x + q2.x + bv,
                                p[0][1] + q0.y + q1.y + q2.y + bv,
                                p[0][2] + q0.z + q1.z + q2.z + bv,
                                p[0][3] + q0.w + q1.w + q2.w + bv };
#pragma unroll
                for (int g = 0; g < G; g++) {
                    float a = tanhf(vv[g]);
                    int idx = g * 256 + jglob;
                    sm->shh0[idx] = a;
                    st_peer_f1(pShh0 + (uint32_t)idx * 4u, a);
                }
            }
        }
        CLUSTER_SYNC();  // CS4

        // ---- new_state layer2 (256->own 128 cols) + masked update ----
        {
            const ulonglong2* Wg[1] = { WP + OFF_NS2 + r256q };
            float p[1][G];
            gemv_part<32, 1, 256, 4>(p, Wg, sm->shh0 + a256q, 256, jglob);
            if (kq != 3)
                *(float4*)&sm->Q[0][kq][jloc][0] =
                    make_float4(p[0][0], p[0][1], p[0][2], p[0][3]);
            __syncthreads();
            if (kq == 3) {
                float bv = ns_b2[jglob];
                float4 q0 = *(const float4*)&sm->Q[0][0][jloc][0];
                float4 q1 = *(const float4*)&sm->Q[0][1][jloc][0];
                float4 q2 = *(const float4*)&sm->Q[0][2][jloc][0];
                float nsv[G] = { p[0][0] + q0.x + q1.x + q2.x + bv,
                                 p[0][1] + q0.y + q1.y + q2.y + bv,
                                 p[0][2] + q0.z + q1.z + q2.z + bv,
                                 p[0][3] + q0.w + q1.w + q2.w + bv };
#pragma unroll
                for (int g = 0; g < G; g++) {
                    float m    = sm->smask[g];
                    int idx    = g * 256 + jglob;
                    float yend = sm->sy[idx], ytv = sm->syt[idx];
                    float ny   = (1.f - u[g])  * nsv[g] + u[g]  * yend;
                    float nyt  = (1.f - ut[g]) * nsv[g] + ut[g] * ytv;
                    float oy   = m * ny  + (1.f - m) * yend;
                    float oyt  = m * nyt + (1.f - m) * ytv;
                    sm->sy[idx]  = oy;
                    sm->syt[idx] = oyt;
                    st_peer_f1(pSy  + (uint32_t)idx * 4u, oy);
                    st_peer_f1(pSyt + (uint32_t)idx * 4u, oyt);
                }
            }
        }
        // next S0 publishes state + protects Q/Pd/act reuse
    }

    CLUSTER_SYNC();
    if (rank == 0 && tid < 256) {
#pragma unroll
        for (int g = 0; g < G; g++)
            out_prev[(size_t)(tb + g) * LATENT + tid] = sm->sy[g * 256 + tid];
    }
}

extern "C" void kernel_launch(void* const* d_in, const int* in_sizes, int n_in,
                              void* d_out, int out_size) {
    const float* data   = (const float*)d_in[0];
    const float* ts     = (const float*)d_in[1];
    const float* ug_w1  = (const float*)d_in[2];
    const float* ug_b1  = (const float*)d_in[3];
    const float* ug_w2  = (const float*)d_in[4];
    const float* ug_b2  = (const float*)d_in[5];
    const float* ugt_w1 = (const float*)d_in[6];
    const float* ugt_b1 = (const float*)d_in[7];
    const float* ugt_w2 = (const float*)d_in[8];
    const float* ugt_b2 = (const float*)d_in[9];
    const float* rg_w1  = (const float*)d_in[10];
    const float* rg_b1  = (const float*)d_in[11];
    const float* rg_w2  = (const float*)d_in[12];
    const float* rg_b2  = (const float*)d_in[13];
    // d_in[14..17] = rgt_* : unused by the reference
    const float* ns_w1  = (const float*)d_in[18];
    const float* ns_b1  = (const float*)d_in[19];
    const float* ns_w2  = (const float*)d_in[20];
    const float* ns_b2  = (const float*)d_in[21];
    const float* dk_w1  = (const float*)d_in[22];
    const float* dk_b1  = (const float*)d_in[23];
    const float* dk_w2  = (const float*)d_in[24];
    const float* dk_b2  = (const float*)d_in[25];
    const float* dec_w  = (const float*)d_in[26];
    const float* dec_b  = (const float*)d_in[27];

    cudaFuncSetAttribute(rnn_decay_kernel,
                         cudaFuncAttributeMaxDynamicSharedMemorySize, SMEM_BYTES);

    pack_kernel<<<(WP_TOTAL + 255) / 256, 256>>>(
        ug_w1, ugt_w1, rg_w1, ns_w1, ug_w2, ugt_w2, rg_w2, ns_w2, dk_w1, dec_w);

    rnn_decay_kernel<<<NBLK, THREADS, SMEM_BYTES>>>(
        data, ts,
        ug_b1, ug_b2, ugt_b1, ugt_b2, rg_b1, rg_b2,
        ns_b1, ns_b2, dk_b1, dk_w2, dk_b2, dec_b,
        (float*)d_out);
}